// round 2
// baseline (speedup 1.0000x reference)
#include <cuda_runtime.h>
#include <cuda_bf16.h>

#define B_  16
#define T_  8192
#define TP_ 512
#define E_  256

// ---------------- device scratch (allocations are forbidden) ----------------
__device__ __align__(16) float g_S [B_*TP_*E_];   // enc + enc@W_pos   (8 MB)
__device__ __align__(16) float g_P [T_*E_];       // pe@W_pos + b_pos  (8 MB)
__device__ __align__(16) float g_pe[T_*E_];       // sinusoid PE       (8 MB)
__device__ __align__(16) int   g_idx[B_*T_];      // aligner indices   (512 KB)

// =====================================================================
// Kernel 1: PE table (blocks 0..4095) + exact aligner scan (block 4096)
// =====================================================================
__global__ void __launch_bounds__(256) prep_kernel(const int* __restrict__ align_phone,
                                                   const int* __restrict__ text_phone)
{
    if (blockIdx.x < (T_*128)/256) {
        // ---- sinusoid PE, fp32 angle semantics matching the reference ----
        int gid = blockIdx.x * 256 + threadIdx.x;   // t*128 + i
        int t = gid >> 7;
        int i = gid & 127;
        const float NEGC = -0.03597789202637730f;   // -ln(10000)/E
        float div = expf((float)(2*i) * NEGC);
        float ang = (float)t * div;
        float s, c;
        sincosf(ang, &s, &c);
        ((float2*)g_pe)[gid] = make_float2(s, c);   // pe[t,2i]=sin, pe[t,2i+1]=cos
        return;
    }

    // ---------------- aligner scan (one block) ----------------
    __shared__ short stext[B_*TP_];                 // 16 KB (phone ids fit in 16 bits)
    __shared__ __align__(16) int stage[2][B_*132];  // double-buffered, padded stride
    int tid = threadIdx.x;
    for (int j = tid; j < B_*TP_; j += 256) stext[j] = (short)text_phone[j];
    for (int j = tid; j < B_*128; j += 256) {       // phase 0
        int bb = j >> 7, tt = j & 127;
        stage[0][bb*132 + tt] = align_phone[bb*T_ + tt];
    }
    __syncthreads();

    int b = tid;                                    // lanes 0..15 scan
    int ind = 0, before = 0, nxt = 0;
    if (b < B_) {
        before = (int)stext[b*TP_ + 0];
        nxt    = (int)stext[b*TP_ + 1];
    }

    const int NPH = T_ / 128;                       // 64 phases
    for (int ph = 0; ph < NPH; ph++) {
        int buf = ph & 1;
        // prefetch next phase (loader threads), overlaps with the scan chain
        if (ph + 1 < NPH && tid >= 32) {
            int base = (ph + 1) * 128;
            for (int j = tid - 32; j < B_*128; j += 224) {
                int bb = j >> 7, tt = j & 127;
                stage[buf ^ 1][bb*132 + tt] = align_phone[bb*T_ + base + tt];
            }
        }
        if (b < B_) {
            const int4*  sp = (const int4*)(stage[buf] + b*132);
            const short* tx = stext + b*TP_;
            int* op = g_idx + b*T_ + ph*128;
            for (int cc = 0; cc < 8; cc++) {        // chunks of 16 timesteps
                int cglob = ph*8 + cc;
                int4 c0 = sp[cc*4+0], c1 = sp[cc*4+1], c2 = sp[cc*4+2], c3 = sp[cc*4+3];
                int a0 = c0.x;
                int uni = (c0.y^a0)|(c0.z^a0)|(c0.w^a0)
                        | (c1.x^a0)|(c1.y^a0)|(c1.z^a0)|(c1.w^a0)
                        | (c2.x^a0)|(c2.y^a0)|(c2.z^a0)|(c2.w^a0)
                        | (c3.x^a0)|(c3.y^a0)|(c3.z^a0)|(c3.w^a0);
                bool handled = false;
                if (uni == 0 && cglob != 0) {
                    if (a0 == before) {
                        handled = true;             // whole chunk same phone
                    } else if (a0 == nxt) {
                        ind    = min(ind + 1, TP_-1);
                        before = nxt;               // == tx[new ind]
                        nxt    = (int)tx[min(ind + 1, TP_-1)];
                        handled = true;
                    }
                    if (handled) {
                        int4 s4 = make_int4(ind, ind, ind, ind);
                        int4* o4 = (int4*)(op + cc*16);
                        o4[0] = s4; o4[1] = s4; o4[2] = s4; o4[3] = s4;
                    }
                }
                if (!handled) {                     // general (exact) path
                    int v[16] = {c0.x,c0.y,c0.z,c0.w, c1.x,c1.y,c1.z,c1.w,
                                 c2.x,c2.y,c2.z,c2.w, c3.x,c3.y,c3.z,c3.w};
                    int bufi[16];
                    #pragma unroll
                    for (int j2 = 0; j2 < 16; j2++) {
                        if (j2 == 0 && cglob == 0) {
                            bufi[0] = 0;            // idx[:,0] = 0; scan starts at t=1
                        } else {
                            if (v[j2] != before) {
                                ind    = min(ind + 1, TP_-1);
                                before = (int)tx[ind];
                            }
                            bufi[j2] = ind;
                        }
                    }
                    nxt = (int)tx[min(ind + 1, TP_-1)];
                    int4* o4 = (int4*)(op + cc*16);
                    o4[0] = make_int4(bufi[0], bufi[1], bufi[2], bufi[3]);
                    o4[1] = make_int4(bufi[4], bufi[5], bufi[6], bufi[7]);
                    o4[2] = make_int4(bufi[8], bufi[9], bufi[10],bufi[11]);
                    o4[3] = make_int4(bufi[12],bufi[13],bufi[14],bufi[15]);
                }
            }
        }
        __syncthreads();
    }
}

// =====================================================================
// Kernel 2: fused GEMM, M=16384 (8192 enc rows + 8192 pe rows), N=K=256
//   rows <  8192:  S = enc + enc@W_pos
//   rows >= 8192:  P = pe@W_pos + b_pos
// =====================================================================
#define BM 128
#define BN 64
#define BK 16

__global__ void __launch_bounds__(256) gemm_kernel(const float* __restrict__ enc,
                                                   const float* __restrict__ Wpos,
                                                   const float* __restrict__ bpos)
{
    __shared__ __align__(16) float As[BK][BM + 4];
    __shared__ __align__(16) float Bs[BK][BN];

    int tid   = threadIdx.x;
    int mBase = blockIdx.x * BM;
    int nBase = blockIdx.y * BN;
    bool isEnc = (mBase < B_*TP_);
    const float* A = isEnc ? enc : (const float*)g_pe;
    int mOff = isEnc ? mBase : (mBase - B_*TP_);

    int tx = tid & 15;          // 16 n-groups of 4
    int ty = tid >> 4;          // 16 m-groups of 8

    float acc[8][4];
    #pragma unroll
    for (int im = 0; im < 8; im++)
        #pragma unroll
        for (int jn = 0; jn < 4; jn++) acc[im][jn] = 0.f;

    for (int kB = 0; kB < E_; kB += BK) {
        #pragma unroll
        for (int j = 0; j < 2; j++) {               // A tile (128x16) -> As[k][m]
            int li  = tid*2 + j;
            int row = li >> 2;
            int c4  = li & 3;
            float4 v = *(const float4*)&A[(size_t)(mOff + row)*E_ + kB + c4*4];
            As[c4*4+0][row] = v.x;
            As[c4*4+1][row] = v.y;
            As[c4*4+2][row] = v.z;
            As[c4*4+3][row] = v.w;
        }
        {                                            // B tile (16x64)
            int row = tid >> 4;
            int n4  = tid & 15;
            *(float4*)&Bs[row][n4*4] =
                *(const float4*)&Wpos[(size_t)(kB + row)*E_ + nBase + n4*4];
        }
        __syncthreads();

        #pragma unroll
        for (int k = 0; k < BK; k++) {
            float4 a0 = *(const float4*)&As[k][ty*8];
            float4 a1 = *(const float4*)&As[k][ty*8 + 4];
            float4 bv = *(const float4*)&Bs[k][tx*4];
            float am[8] = {a0.x,a0.y,a0.z,a0.w, a1.x,a1.y,a1.z,a1.w};
            float bn[4] = {bv.x,bv.y,bv.z,bv.w};
            #pragma unroll
            for (int im = 0; im < 8; im++)
                #pragma unroll
                for (int jn = 0; jn < 4; jn++)
                    acc[im][jn] = fmaf(am[im], bn[jn], acc[im][jn]);
        }
        __syncthreads();
    }

    int n = nBase + tx*4;
    if (isEnc) {
        #pragma unroll
        for (int im = 0; im < 8; im++) {
            int m = mBase + ty*8 + im;
            float4 e = *(const float4*)&enc[(size_t)m*E_ + n];
            float4 o = make_float4(acc[im][0] + e.x, acc[im][1] + e.y,
                                   acc[im][2] + e.z, acc[im][3] + e.w);
            *(float4*)&g_S[(size_t)m*E_ + n] = o;
        }
    } else {
        float4 bp = *(const float4*)&bpos[n];
        #pragma unroll
        for (int im = 0; im < 8; im++) {
            int m = (mBase - B_*TP_) + ty*8 + im;
            float4 o = make_float4(acc[im][0] + bp.x, acc[im][1] + bp.y,
                                   acc[im][2] + bp.z, acc[im][3] + bp.w);
            *(float4*)&g_P[(size_t)m*E_ + n] = o;
        }
    }
}

// =====================================================================
// Kernel 3: streaming assemble
// out[b,t,:] = S[b,idx[b,t],:] + P[t,:] + pitch[b,t]*W_pitch + b_pitch
//              + emb_beats[beats[b,t],:]
// =====================================================================
__global__ void __launch_bounds__(256) main_kernel(const float* __restrict__ pitch,
                                                   const int*   __restrict__ beats,
                                                   const float* __restrict__ Wpitch,
                                                   const float* __restrict__ bpitch,
                                                   const float* __restrict__ embBeats,
                                                   float* __restrict__ out)
{
    int gid = blockIdx.x * 256 + threadIdx.x;   // B*T*64 float4 slots
    int e4  = gid & 63;
    int bt  = gid >> 6;
    int t   = bt & (T_ - 1);
    int b   = bt >> 13;

    int  idx = g_idx[bt];
    float4 s = *(const float4*)&g_S[((size_t)(b*TP_ + idx))*E_ + e4*4];
    float4 p = *(const float4*)&g_P[(size_t)t*E_ + e4*4];
    float  pv = pitch[bt];
    int    bv = beats[bt];
    float4 wp = ((const float4*)Wpitch)[e4];
    float4 bp = ((const float4*)bpitch)[e4];
    float4 eb = *(const float4*)&embBeats[(size_t)bv*E_ + e4*4];

    float4 o;
    o.x = s.x + p.x + fmaf(pv, wp.x, bp.x) + eb.x;
    o.y = s.y + p.y + fmaf(pv, wp.y, bp.y) + eb.y;
    o.z = s.z + p.z + fmaf(pv, wp.z, bp.z) + eb.z;
    o.w = s.w + p.w + fmaf(pv, wp.w, bp.w) + eb.w;
    ((float4*)out)[gid] = o;
}

// =====================================================================
extern "C" void kernel_launch(void* const* d_in, const int* in_sizes, int n_in,
                              void* d_out, int out_size)
{
    const float* enc      = (const float*)d_in[0];
    const int*   align_p  = (const int*)  d_in[1];
    const int*   text_p   = (const int*)  d_in[2];
    const float* pitch    = (const float*)d_in[3];
    const int*   beats    = (const int*)  d_in[4];
    const float* W_pitch  = (const float*)d_in[5];
    const float* b_pitch  = (const float*)d_in[6];
    const float* W_pos    = (const float*)d_in[7];
    const float* b_pos    = (const float*)d_in[8];
    const float* emb_b    = (const float*)d_in[9];
    float* out = (float*)d_out;

    // PE (4096 blocks) + aligner scan (1 block) run concurrently in one launch
    prep_kernel<<<(T_*128)/256 + 1, 256>>>(align_p, text_p);

    dim3 ggrid((B_*TP_ + T_) / BM, E_ / BN);
    gemm_kernel<<<ggrid, 256>>>(enc, W_pos, b_pos);

    main_kernel<<<(B_*T_*(E_/4)) / 256, 256>>>(pitch, beats, W_pitch, b_pitch,
                                               emb_b, out);
}

// round 3
// speedup vs baseline: 1.4314x; 1.4314x over previous
#include <cuda_runtime.h>
#include <cuda_bf16.h>

#define B_  16
#define T_  8192
#define TP_ 512
#define E_  256
#define FULLMASK 0xFFFFFFFFu

// ---------------- device scratch (allocations are forbidden) ----------------
__device__ __align__(16) float g_S [B_*TP_*E_];   // enc + enc@W_pos   (8 MB)
__device__ __align__(16) float g_P [T_*E_];       // pe@W_pos + b_pos  (8 MB)
__device__ __align__(16) float g_pe[T_*E_];       // sinusoid PE       (8 MB)
__device__ __align__(16) int   g_idx[B_*T_];      // aligner indices   (512 KB)

// =====================================================================
// Kernel 1: PE table (blocks 0..255, rotation trick) +
//           exact aligner scan (block 256, one warp per batch)
// =====================================================================
__global__ void __launch_bounds__(512) prep_kernel(const int* __restrict__ align_phone,
                                                   const int* __restrict__ text_phone)
{
    if (blockIdx.x < 256) {
        // ---- sinusoid PE: 2 sincosf per 8 timesteps via rotation ----
        int g  = blockIdx.x * 512 + threadIdx.x;   // [0, 131072)
        int i  = g & 127;                          // freq index
        int tb = g >> 7;                           // [0, 1024)
        int t0 = tb * 8;
        const float NEGC = -0.03597789202637730f;  // -ln(10000)/E
        float div = expf((float)(2*i) * NEGC);
        float s, c, sd, cd;
        sincosf((float)t0 * div, &s, &c);
        sincosf(div, &sd, &cd);
        float2* row = ((float2*)g_pe) + (size_t)t0*128 + i;
        #pragma unroll
        for (int r = 0; r < 8; r++) {
            row[(size_t)r*128] = make_float2(s, c);
            float s2 = fmaf(s, cd,  c*sd);
            float c2 = fmaf(c, cd, -s*sd);
            s = s2; c = c2;
        }
        return;
    }

    // ---------------- aligner scan: warp w handles batch w ----------------
    __shared__ short stext[B_][TP_];               // 16 KB (phone ids < 64)
    int tid  = threadIdx.x;
    int w    = tid >> 5;
    int lane = tid & 31;
    for (int j = tid; j < B_*TP_; j += 512)
        stext[j >> 9][j & 511] = (short)text_phone[j];
    __syncthreads();

    const short* tx   = stext[w];
    const int*   arow = align_phone + (size_t)w * T_;
    int*         orow = g_idx       + (size_t)w * T_;

    // state (replicated on all lanes): invariant before==tx[ind],
    // nxt==tx[min(ind+1,511)], nxt2==tx[min(ind+2,511)]
    int ind = 0;
    int before = (int)tx[0];
    int nxt    = (int)tx[1];
    int nxt2   = (int)tx[2];

#define ADVANCE() do {                                  \
        ind    = min(ind + 1, TP_-1);                   \
        before = nxt;                                   \
        nxt    = nxt2;                                  \
        nxt2   = (int)tx[min(ind + 2, TP_-1)];          \
    } while (0)

    // 256 chunks of 32 timesteps; prefetch one 8-chunk group ahead
    int vA[8], vB[8];
    #pragma unroll
    for (int g2 = 0; g2 < 8; g2++) vA[g2] = arow[g2*32 + lane];

    for (int grp = 0; grp < 32; grp++) {
        if (grp + 1 < 32) {
            #pragma unroll
            for (int g2 = 0; g2 < 8; g2++)
                vB[g2] = arow[((grp+1)*8 + g2)*32 + lane];
        }
        #pragma unroll
        for (int g2 = 0; g2 < 8; g2++) {
            int c  = grp*8 + g2;
            int v  = vA[g2];
            int fA = __shfl_sync(FULLMASK, v, 0);
            int fB = __shfl_sync(FULLMASK, v, 16);
            int refv = (lane < 16) ? fA : fB;
            unsigned eq = __ballot_sync(FULLMASK, v == refv);
            bool uniA = ((eq & 0xFFFFu) == 0xFFFFu);
            bool uniB = ((eq >> 16)     == 0xFFFFu);

            int myout = 0;
            #pragma unroll
            for (int h = 0; h < 2; h++) {
                int  l0    = h * 16;
                int  f     = h ? fB : fA;
                bool uni   = h ? uniB : uniA;
                bool t0half = (c == 0 && h == 0);   // half containing t==0
                int  out;
                if (uni && f == before) {
                    out = ind;                       // whole half same phone
                } else if (uni && f == nxt && !t0half) {
                    ADVANCE();                       // single boundary at half start
                    out = ind;
                } else {
                    // exact general path: 16 serial steps
                    out = ind;
                    for (int j = 0; j < 16; j++) {
                        int vj = __shfl_sync(FULLMASK, v, l0 + j);
                        bool isT0 = t0half && (j == 0);
                        if (!isT0 && vj != before) ADVANCE();
                        if (lane == l0 + j) out = ind;
                    }
                }
                if ((lane >> 4) == h) myout = out;
            }
            orow[c*32 + lane] = myout;
        }
        #pragma unroll
        for (int g2 = 0; g2 < 8; g2++) vA[g2] = vB[g2];
    }
#undef ADVANCE
}

// =====================================================================
// Kernel 2: fused GEMM, M=16384 (8192 enc rows + 8192 pe rows), N=K=256
//   rows <  8192:  S = enc + enc@W_pos
//   rows >= 8192:  P = pe@W_pos + b_pos
// =====================================================================
#define BM 128
#define BN 64
#define BK 16

__global__ void __launch_bounds__(256) gemm_kernel(const float* __restrict__ enc,
                                                   const float* __restrict__ Wpos,
                                                   const float* __restrict__ bpos)
{
    __shared__ __align__(16) float As[BK][BM + 4];
    __shared__ __align__(16) float Bs[BK][BN];

    int tid   = threadIdx.x;
    int mBase = blockIdx.x * BM;
    int nBase = blockIdx.y * BN;
    bool isEnc = (mBase < B_*TP_);
    const float* A = isEnc ? enc : (const float*)g_pe;
    int mOff = isEnc ? mBase : (mBase - B_*TP_);

    int tx = tid & 15;          // 16 n-groups of 4
    int ty = tid >> 4;          // 16 m-groups of 8

    float acc[8][4];
    #pragma unroll
    for (int im = 0; im < 8; im++)
        #pragma unroll
        for (int jn = 0; jn < 4; jn++) acc[im][jn] = 0.f;

    for (int kB = 0; kB < E_; kB += BK) {
        #pragma unroll
        for (int j = 0; j < 2; j++) {               // A tile (128x16) -> As[k][m]
            int li  = tid*2 + j;
            int row = li >> 2;
            int c4  = li & 3;
            float4 v = *(const float4*)&A[(size_t)(mOff + row)*E_ + kB + c4*4];
            As[c4*4+0][row] = v.x;
            As[c4*4+1][row] = v.y;
            As[c4*4+2][row] = v.z;
            As[c4*4+3][row] = v.w;
        }
        {                                            // B tile (16x64)
            int row = tid >> 4;
            int n4  = tid & 15;
            *(float4*)&Bs[row][n4*4] =
                *(const float4*)&Wpos[(size_t)(kB + row)*E_ + nBase + n4*4];
        }
        __syncthreads();

        #pragma unroll
        for (int k = 0; k < BK; k++) {
            float4 a0 = *(const float4*)&As[k][ty*8];
            float4 a1 = *(const float4*)&As[k][ty*8 + 4];
            float4 bv = *(const float4*)&Bs[k][tx*4];
            float am[8] = {a0.x,a0.y,a0.z,a0.w, a1.x,a1.y,a1.z,a1.w};
            float bn[4] = {bv.x,bv.y,bv.z,bv.w};
            #pragma unroll
            for (int im = 0; im < 8; im++)
                #pragma unroll
                for (int jn = 0; jn < 4; jn++)
                    acc[im][jn] = fmaf(am[im], bn[jn], acc[im][jn]);
        }
        __syncthreads();
    }

    int n = nBase + tx*4;
    if (isEnc) {
        #pragma unroll
        for (int im = 0; im < 8; im++) {
            int m = mBase + ty*8 + im;
            float4 e = *(const float4*)&enc[(size_t)m*E_ + n];
            float4 o = make_float4(acc[im][0] + e.x, acc[im][1] + e.y,
                                   acc[im][2] + e.z, acc[im][3] + e.w);
            *(float4*)&g_S[(size_t)m*E_ + n] = o;
        }
    } else {
        float4 bp = *(const float4*)&bpos[n];
        #pragma unroll
        for (int im = 0; im < 8; im++) {
            int m = (mBase - B_*TP_) + ty*8 + im;
            float4 o = make_float4(acc[im][0] + bp.x, acc[im][1] + bp.y,
                                   acc[im][2] + bp.z, acc[im][3] + bp.w);
            *(float4*)&g_P[(size_t)m*E_ + n] = o;
        }
    }
}

// =====================================================================
// Kernel 3: streaming assemble
// out[b,t,:] = S[b,idx[b,t],:] + P[t,:] + pitch[b,t]*W_pitch + b_pitch
//              + emb_beats[beats[b,t],:]
// =====================================================================
__global__ void __launch_bounds__(256) main_kernel(const float* __restrict__ pitch,
                                                   const int*   __restrict__ beats,
                                                   const float* __restrict__ Wpitch,
                                                   const float* __restrict__ bpitch,
                                                   const float* __restrict__ embBeats,
                                                   float* __restrict__ out)
{
    int gid = blockIdx.x * 256 + threadIdx.x;   // B*T*64 float4 slots
    int e4  = gid & 63;
    int bt  = gid >> 6;
    int t   = bt & (T_ - 1);
    int b   = bt >> 13;

    int  idx = g_idx[bt];
    float4 s = *(const float4*)&g_S[((size_t)(b*TP_ + idx))*E_ + e4*4];
    float4 p = *(const float4*)&g_P[(size_t)t*E_ + e4*4];
    float  pv = pitch[bt];
    int    bv = beats[bt];
    float4 wp = ((const float4*)Wpitch)[e4];
    float4 bp = ((const float4*)bpitch)[e4];
    float4 eb = *(const float4*)&embBeats[(size_t)bv*E_ + e4*4];

    float4 o;
    o.x = s.x + p.x + fmaf(pv, wp.x, bp.x) + eb.x;
    o.y = s.y + p.y + fmaf(pv, wp.y, bp.y) + eb.y;
    o.z = s.z + p.z + fmaf(pv, wp.z, bp.z) + eb.z;
    o.w = s.w + p.w + fmaf(pv, wp.w, bp.w) + eb.w;
    ((float4*)out)[gid] = o;
}

// =====================================================================
extern "C" void kernel_launch(void* const* d_in, const int* in_sizes, int n_in,
                              void* d_out, int out_size)
{
    const float* enc      = (const float*)d_in[0];
    const int*   align_p  = (const int*)  d_in[1];
    const int*   text_p   = (const int*)  d_in[2];
    const float* pitch    = (const float*)d_in[3];
    const int*   beats    = (const int*)  d_in[4];
    const float* W_pitch  = (const float*)d_in[5];
    const float* b_pitch  = (const float*)d_in[6];
    const float* W_pos    = (const float*)d_in[7];
    const float* b_pos    = (const float*)d_in[8];
    const float* emb_b    = (const float*)d_in[9];
    float* out = (float*)d_out;

    // PE (256 blocks) + aligner scan (1 block) concurrently in one launch
    prep_kernel<<<257, 512>>>(align_p, text_p);

    dim3 ggrid((B_*TP_ + T_) / BM, E_ / BN);
    gemm_kernel<<<ggrid, 256>>>(enc, W_pos, b_pos);

    main_kernel<<<(B_*T_*(E_/4)) / 256, 256>>>(pitch, beats, W_pitch, b_pitch,
                                               emb_b, out);
}

// round 4
// speedup vs baseline: 1.7478x; 1.2211x over previous
#include <cuda_runtime.h>
#include <cuda_bf16.h>

#define B_  16
#define T_  8192
#define TP_ 512
#define E_  256
#define FULLMASK 0xFFFFFFFFu

// ---------------- device scratch (allocations are forbidden) ----------------
__device__ __align__(16) float g_S [B_*TP_*E_];   // enc + enc@W_pos   (8 MB)
__device__ __align__(16) float g_P [T_*E_];       // pe@W_pos + b_pos  (8 MB)
__device__ __align__(16) float g_pe[T_*E_];       // sinusoid PE       (8 MB)
__device__ __align__(16) int   g_idx[B_*T_];      // aligner indices   (512 KB)

// =====================================================================
// Kernel 1: PE table (blocks 0..255, rotation trick) +
//           exact aligner scan (block 256, one warp per batch,
//           group-of-256 validate-then-jump)
// =====================================================================
__global__ void __launch_bounds__(512) prep_kernel(const int* __restrict__ align_phone,
                                                   const int* __restrict__ text_phone)
{
    if (blockIdx.x < 256) {
        // ---- sinusoid PE: 2 sincosf per 8 timesteps via rotation ----
        int g  = blockIdx.x * 512 + threadIdx.x;   // [0, 131072)
        int i  = g & 127;                          // freq index
        int tb = g >> 7;                           // [0, 1024)
        int t0 = tb * 8;
        const float NEGC = -0.03597789202637730f;  // -ln(10000)/E
        float div = expf((float)(2*i) * NEGC);
        float s, c, sd, cd;
        sincosf((float)t0 * div, &s, &c);
        sincosf(div, &sd, &cd);
        float2* row = ((float2*)g_pe) + (size_t)t0*128 + i;
        #pragma unroll
        for (int r = 0; r < 8; r++) {
            row[(size_t)r*128] = make_float2(s, c);
            float s2 = fmaf(s, cd,  c*sd);
            float c2 = fmaf(c, cd, -s*sd);
            s = s2; c = c2;
        }
        return;
    }

    // ---------------- aligner scan: warp w handles batch w ----------------
    __shared__ short stext[B_][TP_];               // 16 KB (phone ids < 64)
    int tid  = threadIdx.x;
    int w    = tid >> 5;
    int lane = tid & 31;
    for (int j = tid; j < B_*TP_; j += 512)
        stext[j >> 9][j & 511] = (short)text_phone[j];
    __syncthreads();

    const short* tx   = stext[w];
    const int*   arow = align_phone + (size_t)w * T_;
    int*         orow = g_idx       + (size_t)w * T_;

    // FSM state, warp-uniform. Invariant: before == tx[ind].
    int ind    = 0;
    int before = (int)tx[0];

    // double-buffered group loads: 256 elements per group, 8 regs/lane
    int vA[8], vB[8];
    #pragma unroll
    for (int g2 = 0; g2 < 8; g2++) vA[g2] = arow[g2*32 + lane];

    for (int g = 0; g < 32; g++) {
        if (g + 1 < 32) {
            #pragma unroll
            for (int g2 = 0; g2 < 8; g2++)
                vB[g2] = arow[(g+1)*256 + g2*32 + lane];
        }

        // Expected trajectory for this group if every 16-aligned subblock is
        // one full run: subblock j holds phone tx[base+j], output base+j.
        int base = (g == 0) ? 0 : ind + 1;
        bool inrange = (base + 15 <= TP_ - 1);

        // lanes 0..15 hold the text window tx[base..base+15]
        int tw  = (int)tx[min(base + (lane & 15), TP_ - 1)];
        int twp = __shfl_up_sync(FULLMASK, tw, 1);
        // window must be pairwise-distinct (incl. vs current `before`) for the
        // jump to be provably identical to the exact FSM
        bool headok = ((lane & 15) == 0) ? ((g == 0) || (tw != before))
                                         : (tw != twp);
        unsigned dmask = __ballot_sync(FULLMASK, headok);
        bool ok = inrange && ((dmask & 0xFFFFu) == 0xFFFFu);

        #pragma unroll
        for (int g2 = 0; g2 < 8; g2++) {
            int e0 = __shfl_sync(FULLMASK, tw, 2*g2);      // subblock 2*g2
            int e1 = __shfl_sync(FULLMASK, tw, 2*g2 + 1);  // subblock 2*g2+1
            int expv = (lane < 16) ? e0 : e1;
            unsigned m = __ballot_sync(FULLMASK, vA[g2] == expv);
            if (g == 0 && g2 == 0) m |= 1u;                // t==0 value is ignored
            ok &= (m == FULLMASK);
        }

        if (ok) {                                          // warp-uniform branch
            #pragma unroll
            for (int g2 = 0; g2 < 8; g2++)
                orow[g*256 + g2*32 + lane] = base + g2*2 + (lane >> 4);
            ind    = base + 15;
            before = __shfl_sync(FULLMASK, tw, 15);
        } else {
            // exact serial fallback over the 256 elements of this group
            #pragma unroll
            for (int g2 = 0; g2 < 8; g2++) {
                int outv = 0;
                #pragma unroll 1
                for (int j = 0; j < 32; j++) {
                    int vj = __shfl_sync(FULLMASK, vA[g2], j);
                    bool isT0 = (g == 0 && g2 == 0 && j == 0);
                    if (!isT0 && vj != before) {
                        ind    = min(ind + 1, TP_ - 1);
                        before = (int)tx[ind];
                    }
                    if (lane == j) outv = ind;
                }
                orow[g*256 + g2*32 + lane] = outv;
            }
        }

        #pragma unroll
        for (int g2 = 0; g2 < 8; g2++) vA[g2] = vB[g2];
    }
}

// =====================================================================
// Kernel 2: fused GEMM, M=16384 (8192 enc rows + 8192 pe rows), N=K=256
//   rows <  8192:  S = enc + enc@W_pos
//   rows >= 8192:  P = pe@W_pos + b_pos
// =====================================================================
#define BM 128
#define BN 64
#define BK 16

__global__ void __launch_bounds__(256) gemm_kernel(const float* __restrict__ enc,
                                                   const float* __restrict__ Wpos,
                                                   const float* __restrict__ bpos)
{
    __shared__ __align__(16) float As[BK][BM + 4];
    __shared__ __align__(16) float Bs[BK][BN];

    int tid   = threadIdx.x;
    int mBase = blockIdx.x * BM;
    int nBase = blockIdx.y * BN;
    bool isEnc = (mBase < B_*TP_);
    const float* A = isEnc ? enc : (const float*)g_pe;
    int mOff = isEnc ? mBase : (mBase - B_*TP_);

    int tx = tid & 15;          // 16 n-groups of 4
    int ty = tid >> 4;          // 16 m-groups of 8

    float acc[8][4];
    #pragma unroll
    for (int im = 0; im < 8; im++)
        #pragma unroll
        for (int jn = 0; jn < 4; jn++) acc[im][jn] = 0.f;

    for (int kB = 0; kB < E_; kB += BK) {
        #pragma unroll
        for (int j = 0; j < 2; j++) {               // A tile (128x16) -> As[k][m]
            int li  = tid*2 + j;
            int row = li >> 2;
            int c4  = li & 3;
            float4 v = *(const float4*)&A[(size_t)(mOff + row)*E_ + kB + c4*4];
            As[c4*4+0][row] = v.x;
            As[c4*4+1][row] = v.y;
            As[c4*4+2][row] = v.z;
            As[c4*4+3][row] = v.w;
        }
        {                                            // B tile (16x64)
            int row = tid >> 4;
            int n4  = tid & 15;
            *(float4*)&Bs[row][n4*4] =
                *(const float4*)&Wpos[(size_t)(kB + row)*E_ + nBase + n4*4];
        }
        __syncthreads();

        #pragma unroll
        for (int k = 0; k < BK; k++) {
            float4 a0 = *(const float4*)&As[k][ty*8];
            float4 a1 = *(const float4*)&As[k][ty*8 + 4];
            float4 bv = *(const float4*)&Bs[k][tx*4];
            float am[8] = {a0.x,a0.y,a0.z,a0.w, a1.x,a1.y,a1.z,a1.w};
            float bn[4] = {bv.x,bv.y,bv.z,bv.w};
            #pragma unroll
            for (int im = 0; im < 8; im++)
                #pragma unroll
                for (int jn = 0; jn < 4; jn++)
                    acc[im][jn] = fmaf(am[im], bn[jn], acc[im][jn]);
        }
        __syncthreads();
    }

    int n = nBase + tx*4;
    if (isEnc) {
        #pragma unroll
        for (int im = 0; im < 8; im++) {
            int m = mBase + ty*8 + im;
            float4 e = *(const float4*)&enc[(size_t)m*E_ + n];
            float4 o = make_float4(acc[im][0] + e.x, acc[im][1] + e.y,
                                   acc[im][2] + e.z, acc[im][3] + e.w);
            *(float4*)&g_S[(size_t)m*E_ + n] = o;
        }
    } else {
        float4 bp = *(const float4*)&bpos[n];
        #pragma unroll
        for (int im = 0; im < 8; im++) {
            int m = (mBase - B_*TP_) + ty*8 + im;
            float4 o = make_float4(acc[im][0] + bp.x, acc[im][1] + bp.y,
                                   acc[im][2] + bp.z, acc[im][3] + bp.w);
            *(float4*)&g_P[(size_t)m*E_ + n] = o;
        }
    }
}

// =====================================================================
// Kernel 3: streaming assemble
// out[b,t,:] = S[b,idx[b,t],:] + P[t,:] + pitch[b,t]*W_pitch + b_pitch
//              + emb_beats[beats[b,t],:]
// =====================================================================
__global__ void __launch_bounds__(256) main_kernel(const float* __restrict__ pitch,
                                                   const int*   __restrict__ beats,
                                                   const float* __restrict__ Wpitch,
                                                   const float* __restrict__ bpitch,
                                                   const float* __restrict__ embBeats,
                                                   float* __restrict__ out)
{
    int gid = blockIdx.x * 256 + threadIdx.x;   // B*T*64 float4 slots
    int e4  = gid & 63;
    int bt  = gid >> 6;
    int t   = bt & (T_ - 1);
    int b   = bt >> 13;

    int  idx = g_idx[bt];
    float4 s = *(const float4*)&g_S[((size_t)(b*TP_ + idx))*E_ + e4*4];
    float4 p = *(const float4*)&g_P[(size_t)t*E_ + e4*4];
    float  pv = pitch[bt];
    int    bv = beats[bt];
    float4 wp = ((const float4*)Wpitch)[e4];
    float4 bp = ((const float4*)bpitch)[e4];
    float4 eb = *(const float4*)&embBeats[(size_t)bv*E_ + e4*4];

    float4 o;
    o.x = s.x + p.x + fmaf(pv, wp.x, bp.x) + eb.x;
    o.y = s.y + p.y + fmaf(pv, wp.y, bp.y) + eb.y;
    o.z = s.z + p.z + fmaf(pv, wp.z, bp.z) + eb.z;
    o.w = s.w + p.w + fmaf(pv, wp.w, bp.w) + eb.w;
    ((float4*)out)[gid] = o;
}

// =====================================================================
extern "C" void kernel_launch(void* const* d_in, const int* in_sizes, int n_in,
                              void* d_out, int out_size)
{
    const float* enc      = (const float*)d_in[0];
    const int*   align_p  = (const int*)  d_in[1];
    const int*   text_p   = (const int*)  d_in[2];
    const float* pitch    = (const float*)d_in[3];
    const int*   beats    = (const int*)  d_in[4];
    const float* W_pitch  = (const float*)d_in[5];
    const float* b_pitch  = (const float*)d_in[6];
    const float* W_pos    = (const float*)d_in[7];
    const float* b_pos    = (const float*)d_in[8];
    const float* emb_b    = (const float*)d_in[9];
    float* out = (float*)d_out;

    // PE (256 blocks) + aligner scan (1 block) concurrently in one launch
    prep_kernel<<<257, 512>>>(align_p, text_p);

    dim3 ggrid((B_*TP_ + T_) / BM, E_ / BN);
    gemm_kernel<<<ggrid, 256>>>(enc, W_pos, b_pos);

    main_kernel<<<(B_*T_*(E_/4)) / 256, 256>>>(pitch, beats, W_pitch, b_pitch,
                                               emb_b, out);
}

// round 6
// speedup vs baseline: 2.1016x; 1.2024x over previous
#include <cuda_runtime.h>
#include <cuda_bf16.h>
#include <cstdint>

#define B_  16
#define T_  8192
#define TP_ 512
#define E_  256
#define M_TOT (B_*TP_ + T_)     // 16384 GEMM rows: 8192 enc + 8192 pe
#define FULLMASK 0xFFFFFFFFu

// ---------------- device scratch (allocations are forbidden) ----------------
__device__ __align__(16) float          g_S [B_*TP_*E_];   // enc + enc@W_pos   (8 MB)
__device__ __align__(16) float          g_P [T_*E_];       // pe@W_pos + b_pos  (8 MB)
__device__ __align__(16) float          g_pe[T_*E_];       // sinusoid PE       (8 MB)
__device__ __align__(16) int            g_idx[B_*T_];      // aligner indices   (512 KB)
__device__ __align__(16) __nv_bfloat16  gBhi[E_*E_];       // W^T hi (128 KB)
__device__ __align__(16) __nv_bfloat16  gBlo[E_*E_];       // W^T lo (128 KB)

// ---------------- helpers ----------------
__device__ __forceinline__ uint32_t smem_u32(const void* p) {
    uint32_t a;
    asm("{ .reg .u64 t; cvta.to.shared.u64 t, %1; cvt.u32.u64 %0, t; }" : "=r"(a) : "l"(p));
    return a;
}
// SW64 swizzle: 64-byte rows, XOR bits [5:4] with bits [8:7]
#define SWZ64(x) ((x) ^ (((x) >> 3) & 0x30))

__device__ __forceinline__ void ldsm_x4(uint32_t& r0, uint32_t& r1, uint32_t& r2,
                                        uint32_t& r3, uint32_t addr) {
    asm volatile("ldmatrix.sync.aligned.m8n8.x4.shared.b16 {%0,%1,%2,%3}, [%4];"
                 : "=r"(r0), "=r"(r1), "=r"(r2), "=r"(r3) : "r"(addr));
}
__device__ __forceinline__ void mma_bf16(float* c, const uint32_t* a,
                                         uint32_t b0, uint32_t b1) {
    asm volatile(
        "mma.sync.aligned.m16n8k16.row.col.f32.bf16.bf16.f32 "
        "{%0,%1,%2,%3}, {%4,%5,%6,%7}, {%8,%9}, {%0,%1,%2,%3};"
        : "+f"(c[0]), "+f"(c[1]), "+f"(c[2]), "+f"(c[3])
        : "r"(a[0]), "r"(a[1]), "r"(a[2]), "r"(a[3]), "r"(b0), "r"(b1));
}
__device__ __forceinline__ uint32_t pack_bf2(float a, float b) {
    __nv_bfloat162 h(__float2bfloat16_rn(a), __float2bfloat16_rn(b));
    return *reinterpret_cast<uint32_t*>(&h);
}
__device__ __forceinline__ uint32_t pack_lo2(float a, float b) {
    __nv_bfloat16 ha = __float2bfloat16_rn(a), hb = __float2bfloat16_rn(b);
    return pack_bf2(a - __bfloat162float(ha), b - __bfloat162float(hb));
}

// =====================================================================
// Kernel 1 (prep):
//   blocks [0,256)   : sinusoid PE (fp32) via rotation trick
//   block  256       : exact aligner scan (validate-then-jump)
//   blocks [257,385) : W_pos transpose + bf16 hi/lo split
// =====================================================================
__global__ void __launch_bounds__(512) prep_kernel(const int* __restrict__ align_phone,
                                                   const int* __restrict__ text_phone,
                                                   const float* __restrict__ Wpos)
{
    int bid = blockIdx.x, tid = threadIdx.x;

    if (bid < 256) {
        int g  = bid * 512 + tid;                  // [0, 131072)
        int i  = g & 127;
        int t0 = (g >> 7) * 8;
        const float NEGC = -0.03597789202637730f;  // -ln(10000)/E
        float div = expf((float)(2*i) * NEGC);
        float s, c, sd, cd;
        sincosf((float)t0 * div, &s, &c);
        sincosf(div, &sd, &cd);
        float2* row = ((float2*)g_pe) + (size_t)t0*128 + i;
        #pragma unroll
        for (int r = 0; r < 8; r++) {
            row[(size_t)r*128] = make_float2(s, c);
            float s2 = fmaf(s, cd,  c*sd);
            float c2 = fmaf(c, cd, -s*sd);
            s = s2; c = c2;
        }
        return;
    }
    if (bid >= 257) {
        // W_pos transpose + split: Bt[n][k] = W[k][n]
        int idx = (bid - 257) * 512 + tid;         // [0, 65536)
        int k = idx >> 8, n = idx & 255;
        float w2 = Wpos[idx];
        __nv_bfloat16 wh = __float2bfloat16_rn(w2);
        gBhi[n*E_ + k] = wh;
        gBlo[n*E_ + k] = __float2bfloat16_rn(w2 - __bfloat162float(wh));
        return;
    }

    // ---------------- aligner scan (block 256): warp w = batch w ----------------
    __shared__ short stext[B_][TP_];
    int w    = tid >> 5;
    int lane = tid & 31;
    for (int j = tid; j < B_*TP_; j += 512)
        stext[j >> 9][j & 511] = (short)text_phone[j];
    __syncthreads();

    const short* tx   = stext[w];
    const int*   arow = align_phone + (size_t)w * T_;
    int*         orow = g_idx       + (size_t)w * T_;

    int ind = 0;
    int before = (int)tx[0];

    int vA[8], vB[8];
    #pragma unroll
    for (int g2 = 0; g2 < 8; g2++) vA[g2] = arow[g2*32 + lane];

    for (int g = 0; g < 32; g++) {
        if (g + 1 < 32) {
            #pragma unroll
            for (int g2 = 0; g2 < 8; g2++)
                vB[g2] = arow[(g+1)*256 + g2*32 + lane];
        }
        int base = (g == 0) ? 0 : ind + 1;
        bool inrange = (base + 15 <= TP_ - 1);

        int tw  = (int)tx[min(base + (lane & 15), TP_ - 1)];
        int twp = __shfl_up_sync(FULLMASK, tw, 1);
        bool headok = ((lane & 15) == 0) ? ((g == 0) || (tw != before)) : (tw != twp);
        unsigned dmask = __ballot_sync(FULLMASK, headok);
        bool ok = inrange && ((dmask & 0xFFFFu) == 0xFFFFu);

        #pragma unroll
        for (int g2 = 0; g2 < 8; g2++) {
            int e0 = __shfl_sync(FULLMASK, tw, 2*g2);
            int e1 = __shfl_sync(FULLMASK, tw, 2*g2 + 1);
            int expv = (lane < 16) ? e0 : e1;
            unsigned m = __ballot_sync(FULLMASK, vA[g2] == expv);
            if (g == 0 && g2 == 0) m |= 1u;
            ok &= (m == FULLMASK);
        }

        if (ok) {
            #pragma unroll
            for (int g2 = 0; g2 < 8; g2++)
                orow[g*256 + g2*32 + lane] = base + g2*2 + (lane >> 4);
            ind    = base + 15;
            before = __shfl_sync(FULLMASK, tw, 15);
        } else {
            #pragma unroll
            for (int g2 = 0; g2 < 8; g2++) {
                int outv = 0;
                #pragma unroll 1
                for (int j = 0; j < 32; j++) {
                    int vj = __shfl_sync(FULLMASK, vA[g2], j);
                    bool isT0 = (g == 0 && g2 == 0 && j == 0);
                    if (!isT0 && vj != before) {
                        ind    = min(ind + 1, TP_ - 1);
                        before = (int)tx[ind];
                    }
                    if (lane == j) outv = ind;
                }
                orow[g*256 + g2*32 + lane] = outv;
            }
        }
        #pragma unroll
        for (int g2 = 0; g2 < 8; g2++) vA[g2] = vB[g2];
    }
}

// =====================================================================
// Kernel 2: bf16-split tensor-core GEMM via mma.sync (HMMA).
// D[16384,256] = Ahi@Bhi^T + Alo@Bhi^T + Ahi@Blo^T, fp32 accumulate.
// CTA: 128x256 tile; 8 warps of 64x64; K'=768 in 24 chunks of 32;
// double-buffered 48KB static smem, SW64 swizzle; A converted from fp32
// in-register; epilogue adds enc / b_pos and writes g_S / g_P.
// =====================================================================
#define CHK 32                      // K per chunk (floats)
#define ABYTES (128*CHK*2)          // 8 KB
#define BBYTES (256*CHK*2)          // 16 KB
#define BUFB   (ABYTES + BBYTES)    // 24 KB

__global__ void __launch_bounds__(256, 1) gemm_kernel(const float* __restrict__ enc,
                                                      const float* __restrict__ bpos)
{
    __shared__ __align__(128) char smem[2*BUFB];  // 48 KB static
    uint32_t sb = smem_u32(smem);

    int tid  = threadIdx.x;
    int wid  = tid >> 5, lid = tid & 31;
    int wm   = wid & 1;           // warp m (x64)
    int wn   = wid >> 1;          // warp n (x64)
    int g    = lid >> 2, tig = lid & 3;
    int mBase = blockIdx.x * 128;
    bool isEnc = (mBase < B_*TP_);
    const float4* Afp = isEnc ? (const float4*)(enc + (size_t)mBase*E_)
                              : (const float4*)(g_pe + (size_t)(mBase - B_*TP_)*E_);

    float acc[4][8][4];
    #pragma unroll
    for (int t = 0; t < 4; t++)
        #pragma unroll
        for (int u = 0; u < 8; u++)
            #pragma unroll
            for (int q = 0; q < 4; q++) acc[t][u][q] = 0.f;

    // ---- chunk loader: chunk cn -> buffer bsel ----
    auto load_chunk = [&](int cn, int bsel) {
        int seg = cn >> 3;                    // 0: hi*hi, 1: lo*hi, 2: hi*lo
        int kc  = cn & 7;                     // k-slice of 32 within K=256
        bool aLo = (seg == 1);
        const uint4* Bsrc = (seg == 2) ? (const uint4*)gBlo : (const uint4*)gBhi;
        uint32_t ab = sb + bsel*BUFB;
        uint32_t bb = ab + ABYTES;
        #pragma unroll
        for (int i = 0; i < 4; i++) {         // A: 128 rows x 8 float4
            int idx = tid + i*256;
            int row = idx >> 3, c4 = idx & 7;
            float4 v = Afp[(size_t)row*64 + kc*8 + c4];
            uint2 h;
            if (aLo) { h.x = pack_lo2(v.x, v.y); h.y = pack_lo2(v.z, v.w); }
            else     { h.x = pack_bf2(v.x, v.y); h.y = pack_bf2(v.z, v.w); }
            uint32_t off = SWZ64((uint32_t)(row*64 + c4*8));
            *(uint2*)((char*)smem + (ab - sb) + off) = h;
        }
        #pragma unroll
        for (int i = 0; i < 4; i++) {         // B: 256 rows x 4 uint4
            int idx = tid + i*256;
            int row = idx >> 2, c8 = idx & 3;
            uint4 v = Bsrc[(size_t)row*32 + kc*4 + c8];
            uint32_t off = SWZ64((uint32_t)(row*64 + c8*16));
            *(uint4*)((char*)smem + (bb - sb) + off) = v;
        }
    };

    load_chunk(0, 0);
    __syncthreads();

    for (int c = 0; c < 24; c++) {
        if (c + 1 < 24) load_chunk(c + 1, (c + 1) & 1);

        uint32_t ab = sb + (c & 1)*BUFB;
        uint32_t bb = ab + ABYTES;
        #pragma unroll
        for (int ks = 0; ks < 2; ks++) {
            uint32_t af[4][4], bf[8][2];
            #pragma unroll
            for (int t = 0; t < 4; t++) {
                uint32_t off = (uint32_t)((wm*64 + t*16 + (lid & 15))*64
                                          + ks*32 + ((lid >> 4) & 1)*16);
                ldsm_x4(af[t][0], af[t][1], af[t][2], af[t][3], ab + SWZ64(off));
            }
            #pragma unroll
            for (int up = 0; up < 4; up++) {
                uint32_t off = (uint32_t)((wn*64 + up*16 + ((lid >> 4) & 1)*8
                                           + (lid & 7))*64
                                          + ks*32 + ((lid >> 3) & 1)*16);
                ldsm_x4(bf[2*up][0], bf[2*up][1], bf[2*up+1][0], bf[2*up+1][1],
                        bb + SWZ64(off));
            }
            #pragma unroll
            for (int t = 0; t < 4; t++)
                #pragma unroll
                for (int u = 0; u < 8; u++)
                    mma_bf16(acc[t][u], af[t], bf[u][0], bf[u][1]);
        }
        __syncthreads();
    }

    // ---- epilogue ----
    #pragma unroll
    for (int t = 0; t < 4; t++) {
        int rm = mBase + wm*64 + t*16 + g;
        #pragma unroll
        for (int u = 0; u < 8; u++) {
            int n  = wn*64 + u*8 + tig*2;
            int i0 = rm*128 + (n >> 1);          // float2 index row rm
            int i1 = i0 + 8*128;                 // row rm+8
            if (isEnc) {
                float2 e0 = ((const float2*)enc)[i0];
                float2 e1 = ((const float2*)enc)[i1];
                ((float2*)g_S)[i0] = make_float2(acc[t][u][0] + e0.x,
                                                 acc[t][u][1] + e0.y);
                ((float2*)g_S)[i1] = make_float2(acc[t][u][2] + e1.x,
                                                 acc[t][u][3] + e1.y);
            } else {
                float2 bp = ((const float2*)bpos)[n >> 1];
                int j0 = i0 - B_*TP_*128;
                ((float2*)g_P)[j0]         = make_float2(acc[t][u][0] + bp.x,
                                                         acc[t][u][1] + bp.y);
                ((float2*)g_P)[j0 + 8*128] = make_float2(acc[t][u][2] + bp.x,
                                                         acc[t][u][3] + bp.y);
            }
        }
    }
}

// =====================================================================
// Kernel 3: streaming assemble
// out[b,t,:] = S[b,idx,:] + P[t,:] + pitch*W_pitch + b_pitch + emb_beats[beats]
// =====================================================================
__global__ void __launch_bounds__(256) main_kernel(const float* __restrict__ pitch,
                                                   const int*   __restrict__ beats,
                                                   const float* __restrict__ Wpitch,
                                                   const float* __restrict__ bpitch,
                                                   const float* __restrict__ embBeats,
                                                   float* __restrict__ out)
{
    int gid = blockIdx.x * 256 + threadIdx.x;
    int e4  = gid & 63;
    int bt  = gid >> 6;
    int t   = bt & (T_ - 1);
    int b   = bt >> 13;

    int  idx = g_idx[bt];
    float4 s = *(const float4*)&g_S[((size_t)(b*TP_ + idx))*E_ + e4*4];
    float4 p = *(const float4*)&g_P[(size_t)t*E_ + e4*4];
    float  pv = pitch[bt];
    int    bv = beats[bt];
    float4 wp = ((const float4*)Wpitch)[e4];
    float4 bp = ((const float4*)bpitch)[e4];
    float4 eb = *(const float4*)&embBeats[(size_t)bv*E_ + e4*4];

    float4 o;
    o.x = s.x + p.x + fmaf(pv, wp.x, bp.x) + eb.x;
    o.y = s.y + p.y + fmaf(pv, wp.y, bp.y) + eb.y;
    o.z = s.z + p.z + fmaf(pv, wp.z, bp.z) + eb.z;
    o.w = s.w + p.w + fmaf(pv, wp.w, bp.w) + eb.w;
    ((float4*)out)[gid] = o;
}

// =====================================================================
extern "C" void kernel_launch(void* const* d_in, const int* in_sizes, int n_in,
                              void* d_out, int out_size)
{
    const float* enc      = (const float*)d_in[0];
    const int*   align_p  = (const int*)  d_in[1];
    const int*   text_p   = (const int*)  d_in[2];
    const float* pitch    = (const float*)d_in[3];
    const int*   beats    = (const int*)  d_in[4];
    const float* W_pitch  = (const float*)d_in[5];
    const float* b_pitch  = (const float*)d_in[6];
    const float* W_pos    = (const float*)d_in[7];
    const float* b_pos    = (const float*)d_in[8];
    const float* emb_b    = (const float*)d_in[9];
    float* out = (float*)d_out;

    // PE (256) + scan (1) + W split (128) = 385 blocks
    prep_kernel<<<385, 512>>>(align_p, text_p, W_pos);

    gemm_kernel<<<M_TOT/128, 256>>>(enc, b_pos);

    main_kernel<<<(B_*T_*(E_/4)) / 256, 256>>>(pitch, beats, W_pitch, b_pitch,
                                               emb_b, out);
}

// round 7
// speedup vs baseline: 3.0323x; 1.4428x over previous
#include <cuda_runtime.h>
#include <cuda_bf16.h>
#include <cstdint>

#define B_  16
#define T_  8192
#define TP_ 512
#define E_  256
#define M_TOT (B_*TP_ + T_)     // 16384 GEMM rows: 8192 enc + 8192 pe
#define FULLMASK 0xFFFFFFFFu

// ---------------- device scratch (allocations are forbidden) ----------------
__device__ __align__(16) float          g_S [B_*TP_*E_];   // enc + enc@W_pos   (8 MB)
__device__ __align__(16) float          g_P [T_*E_];       // pe@W_pos + b_pos  (8 MB)
__device__ __align__(16) float          g_pe[T_*E_];       // sinusoid PE       (8 MB)
__device__ __align__(16) int            g_idx[B_*T_];      // aligner indices   (512 KB)
__device__ __align__(16) __nv_bfloat16  gBhi[E_*E_];       // W^T hi (128 KB)
__device__ __align__(16) __nv_bfloat16  gBlo[E_*E_];       // W^T lo (128 KB)

// ---------------- helpers ----------------
__device__ __forceinline__ uint32_t smem_u32(const void* p) {
    uint32_t a;
    asm("{ .reg .u64 t; cvta.to.shared.u64 t, %1; cvt.u32.u64 %0, t; }" : "=r"(a) : "l"(p));
    return a;
}
// SW64 swizzle: 64-byte rows, XOR bits [5:4] with bits [8:7]
#define SWZ64(x) ((x) ^ (((x) >> 3) & 0x30))

__device__ __forceinline__ void ldsm_x4(uint32_t& r0, uint32_t& r1, uint32_t& r2,
                                        uint32_t& r3, uint32_t addr) {
    asm volatile("ldmatrix.sync.aligned.m8n8.x4.shared.b16 {%0,%1,%2,%3}, [%4];"
                 : "=r"(r0), "=r"(r1), "=r"(r2), "=r"(r3) : "r"(addr));
}
__device__ __forceinline__ void mma_bf16(float* c, const uint32_t* a,
                                         uint32_t b0, uint32_t b1) {
    asm volatile(
        "mma.sync.aligned.m16n8k16.row.col.f32.bf16.bf16.f32 "
        "{%0,%1,%2,%3}, {%4,%5,%6,%7}, {%8,%9}, {%0,%1,%2,%3};"
        : "+f"(c[0]), "+f"(c[1]), "+f"(c[2]), "+f"(c[3])
        : "r"(a[0]), "r"(a[1]), "r"(a[2]), "r"(a[3]), "r"(b0), "r"(b1));
}
__device__ __forceinline__ uint32_t pack_bf2(float a, float b) {
    __nv_bfloat162 h(__float2bfloat16_rn(a), __float2bfloat16_rn(b));
    return *reinterpret_cast<uint32_t*>(&h);
}
__device__ __forceinline__ uint32_t pack_lo2(float a, float b) {
    __nv_bfloat16 ha = __float2bfloat16_rn(a), hb = __float2bfloat16_rn(b);
    return pack_bf2(a - __bfloat162float(ha), b - __bfloat162float(hb));
}

// =====================================================================
// Kernel 1 (prep):
//   blocks [0,256)   : sinusoid PE (fp32) via rotation trick
//   blocks [256,272) : parallel aligner (prefix-sum + validate, exact)
//   blocks [272,400) : W_pos transpose + bf16 hi/lo split
// =====================================================================
__global__ void __launch_bounds__(512) prep_kernel(const int* __restrict__ align_phone,
                                                   const int* __restrict__ text_phone,
                                                   const float* __restrict__ Wpos)
{
    int bid = blockIdx.x, tid = threadIdx.x;

    if (bid < 256) {
        // ---- sinusoid PE: 2 sincosf per 8 timesteps via rotation ----
        int g  = bid * 512 + tid;                  // [0, 131072)
        int i  = g & 127;
        int t0 = (g >> 7) * 8;
        const float NEGC = -0.03597789202637730f;  // -ln(10000)/E
        float div = expf((float)(2*i) * NEGC);
        float s, c, sd, cd;
        sincosf((float)t0 * div, &s, &c);
        sincosf(div, &sd, &cd);
        float2* row = ((float2*)g_pe) + (size_t)t0*128 + i;
        #pragma unroll
        for (int r = 0; r < 8; r++) {
            row[(size_t)r*128] = make_float2(s, c);
            float s2 = fmaf(s, cd,  c*sd);
            float c2 = fmaf(c, cd, -s*sd);
            s = s2; c = c2;
        }
        return;
    }
    if (bid >= 272) {
        // ---- W_pos transpose + split: Bt[n][k] = W[k][n] ----
        int idx = (bid - 272) * 512 + tid;         // [0, 65536)
        int k = idx >> 8, n = idx & 255;
        float w2 = Wpos[idx];
        __nv_bfloat16 wh = __float2bfloat16_rn(w2);
        gBhi[n*E_ + k] = wh;
        gBlo[n*E_ + k] = __float2bfloat16_rn(w2 - __bfloat162float(wh));
        return;
    }

    // ---------------- parallel aligner: block handles batch b ----------------
    // Exactness: cand_t = clamp(prefix-count of boundaries, 0, 511) equals the
    // reference FSM iff align[0]==text[0] and text[cand_t]==align[t] for all t
    // (induction: FSM's `before` then always equals align[t-1]). Validate that;
    // serial FSM fallback if it ever fails.
    __shared__ short stx[TP_];
    __shared__ int   wsum[16];
    __shared__ int   s_ok;
    int b = bid - 256;
    const int* arow = align_phone + (size_t)b * T_;
    int*       orow = g_idx       + (size_t)b * T_;

    for (int j = tid; j < TP_; j += 512) stx[j] = (short)text_phone[b*TP_ + j];
    if (tid == 0) s_ok = 1;
    __syncthreads();

    int base = tid * 16;
    int v[16];
    #pragma unroll
    for (int q = 0; q < 4; q++)
        *(int4*)&v[q*4] = *(const int4*)&arow[base + q*4];
    int prev = (base == 0) ? v[0] : arow[base - 1];

    unsigned cmask = 0;
    int cnt = 0;
    #pragma unroll
    for (int j = 0; j < 16; j++) {
        int c = (v[j] != prev) ? 1 : 0;
        if (base + j == 0) c = 0;
        cmask |= ((unsigned)c) << j;
        cnt += c;
        prev = v[j];
    }

    // block exclusive scan of per-thread counts (16 warps)
    int lane = tid & 31, wId = tid >> 5;
    int incl = cnt;
    #pragma unroll
    for (int off = 1; off < 32; off <<= 1) {
        int nv = __shfl_up_sync(FULLMASK, incl, off);
        if (lane >= off) incl += nv;
    }
    if (lane == 31) wsum[wId] = incl;
    __syncthreads();
    if (tid == 0) {
        int a = 0;
        #pragma unroll
        for (int i = 0; i < 16; i++) { int t2 = wsum[i]; wsum[i] = a; a += t2; }
    }
    __syncthreads();
    int run = wsum[wId] + incl - cnt;

    bool ok = (base != 0) || (v[0] == (int)stx[0]);
    int outv[16];
    #pragma unroll
    for (int j = 0; j < 16; j++) {
        run += (int)((cmask >> j) & 1u);
        int ind = min(run, TP_ - 1);
        outv[j] = ind;
        if (base + j != 0) ok &= ((int)stx[ind] == v[j]);
    }
    #pragma unroll
    for (int q = 0; q < 4; q++)
        *(int4*)&orow[base + q*4] = *(const int4*)&outv[q*4];

    if (!ok) atomicAnd(&s_ok, 0);
    __syncthreads();
    if (s_ok == 0 && tid == 0) {
        // exact serial fallback (never taken on well-formed data)
        int ind = 0, before = (int)stx[0];
        orow[0] = 0;
        for (int t = 1; t < T_; t++) {
            int a = arow[t];
            if (a != before) { ind = min(ind + 1, TP_ - 1); before = (int)stx[ind]; }
            orow[t] = ind;
        }
    }
}

// =====================================================================
// Kernel 2: bf16-split tensor-core GEMM via mma.sync (HMMA).
// D[16384,256] = Ahi@Bhi^T + Alo@Bhi^T + Ahi@Blo^T, fp32 accumulate.
// CTA: 128x256 tile; 8 warps of 64x64; K=256 in 8 slices of 32; A fp32
// loaded ONCE per slice, hi+lo converted in-register into smem; B hi/lo
// slices loaded per slice; 3 MMA passes per slice reuse Ahi/Bhi fragments.
// Double-buffered 96KB dynamic smem, SW64 swizzle.
// =====================================================================
#define AHI 0
#define ALO 8192
#define BHI 16384
#define BLO 32768
#define BUFSZ 49152
#define SMEM_GEMM (2*BUFSZ)

__global__ void __launch_bounds__(256, 1) gemm_kernel(const float* __restrict__ enc,
                                                      const float* __restrict__ bpos)
{
    extern __shared__ __align__(128) char smem[];
    uint32_t sb = smem_u32(smem);

    int tid  = threadIdx.x;
    int wid  = tid >> 5, lid = tid & 31;
    int wm   = wid & 1;           // warp m (x64)
    int wn   = wid >> 1;          // warp n (x64)
    int g    = lid >> 2, tig = lid & 3;
    int mBase = blockIdx.x * 128;
    bool isEnc = (mBase < B_*TP_);
    const float4* Afp = isEnc ? (const float4*)(enc + (size_t)mBase*E_)
                              : (const float4*)(g_pe + (size_t)(mBase - B_*TP_)*E_);

    float acc[4][8][4];
    #pragma unroll
    for (int t = 0; t < 4; t++)
        #pragma unroll
        for (int u = 0; u < 8; u++)
            #pragma unroll
            for (int q = 0; q < 4; q++) acc[t][u][q] = 0.f;

    auto load_slice = [&](int kc, int bsel) {
        char* buf = smem + bsel*BUFSZ;
        #pragma unroll
        for (int i = 0; i < 4; i++) {         // A: 128 rows x 8 float4, one read
            int idx = tid + i*256;
            int row = idx >> 3, c4 = idx & 7;
            float4 v = Afp[(size_t)row*64 + kc*8 + c4];
            uint2 hi, lo;
            hi.x = pack_bf2(v.x, v.y);  hi.y = pack_bf2(v.z, v.w);
            lo.x = pack_lo2(v.x, v.y);  lo.y = pack_lo2(v.z, v.w);
            uint32_t off = SWZ64((uint32_t)(row*64 + c4*8));
            *(uint2*)(buf + AHI + off) = hi;
            *(uint2*)(buf + ALO + off) = lo;
        }
        #pragma unroll
        for (int i = 0; i < 4; i++) {         // B hi+lo: 256 rows x 4 uint4 each
            int idx = tid + i*256;
            int row = idx >> 2, c8 = idx & 3;
            uint32_t off = SWZ64((uint32_t)(row*64 + c8*16));
            *(uint4*)(buf + BHI + off) = ((const uint4*)gBhi)[(size_t)row*32 + kc*4 + c8];
            *(uint4*)(buf + BLO + off) = ((const uint4*)gBlo)[(size_t)row*32 + kc*4 + c8];
        }
    };

    load_slice(0, 0);
    __syncthreads();

    for (int kc = 0; kc < 8; kc++) {
        if (kc + 1 < 8) load_slice(kc + 1, (kc + 1) & 1);

        uint32_t ab = sb + (kc & 1)*BUFSZ;
        #pragma unroll
        for (int ks = 0; ks < 2; ks++) {
            uint32_t ah[4][4], bh[8][2], aw[4][4], bw[8][2];
            #pragma unroll
            for (int t = 0; t < 4; t++) {
                uint32_t off = (uint32_t)((wm*64 + t*16 + (lid & 15))*64
                                          + ks*32 + ((lid >> 4) & 1)*16);
                ldsm_x4(ah[t][0], ah[t][1], ah[t][2], ah[t][3], ab + AHI + SWZ64(off));
            }
            #pragma unroll
            for (int up = 0; up < 4; up++) {
                uint32_t off = (uint32_t)((wn*64 + up*16 + ((lid >> 4) & 1)*8
                                           + (lid & 7))*64
                                          + ks*32 + ((lid >> 3) & 1)*16);
                ldsm_x4(bh[2*up][0], bh[2*up][1], bh[2*up+1][0], bh[2*up+1][1],
                        ab + BHI + SWZ64(off));
            }
            #pragma unroll
            for (int t = 0; t < 4; t++)
                #pragma unroll
                for (int u = 0; u < 8; u++)
                    mma_bf16(acc[t][u], ah[t], bh[u][0], bh[u][1]);

            #pragma unroll
            for (int t = 0; t < 4; t++) {      // A lo
                uint32_t off = (uint32_t)((wm*64 + t*16 + (lid & 15))*64
                                          + ks*32 + ((lid >> 4) & 1)*16);
                ldsm_x4(aw[t][0], aw[t][1], aw[t][2], aw[t][3], ab + ALO + SWZ64(off));
            }
            #pragma unroll
            for (int t = 0; t < 4; t++)
                #pragma unroll
                for (int u = 0; u < 8; u++)
                    mma_bf16(acc[t][u], aw[t], bh[u][0], bh[u][1]);

            #pragma unroll
            for (int up = 0; up < 4; up++) {   // B lo
                uint32_t off = (uint32_t)((wn*64 + up*16 + ((lid >> 4) & 1)*8
                                           + (lid & 7))*64
                                          + ks*32 + ((lid >> 3) & 1)*16);
                ldsm_x4(bw[2*up][0], bw[2*up][1], bw[2*up+1][0], bw[2*up+1][1],
                        ab + BLO + SWZ64(off));
            }
            #pragma unroll
            for (int t = 0; t < 4; t++)
                #pragma unroll
                for (int u = 0; u < 8; u++)
                    mma_bf16(acc[t][u], ah[t], bw[u][0], bw[u][1]);
        }
        __syncthreads();
    }

    // ---- epilogue ----
    #pragma unroll
    for (int t = 0; t < 4; t++) {
        int rm = mBase + wm*64 + t*16 + g;
        #pragma unroll
        for (int u = 0; u < 8; u++) {
            int n  = wn*64 + u*8 + tig*2;
            int i0 = rm*128 + (n >> 1);          // float2 index row rm
            int i1 = i0 + 8*128;                 // row rm+8
            if (isEnc) {
                float2 e0 = ((const float2*)enc)[i0];
                float2 e1 = ((const float2*)enc)[i1];
                ((float2*)g_S)[i0] = make_float2(acc[t][u][0] + e0.x,
                                                 acc[t][u][1] + e0.y);
                ((float2*)g_S)[i1] = make_float2(acc[t][u][2] + e1.x,
                                                 acc[t][u][3] + e1.y);
            } else {
                float2 bp = ((const float2*)bpos)[n >> 1];
                int j0 = i0 - B_*TP_*128;
                ((float2*)g_P)[j0]         = make_float2(acc[t][u][0] + bp.x,
                                                         acc[t][u][1] + bp.y);
                ((float2*)g_P)[j0 + 8*128] = make_float2(acc[t][u][2] + bp.x,
                                                         acc[t][u][3] + bp.y);
            }
        }
    }
}

// =====================================================================
// Kernel 3: streaming assemble
// out[b,t,:] = S[b,idx,:] + P[t,:] + pitch*W_pitch + b_pitch + emb_beats[beats]
// =====================================================================
__global__ void __launch_bounds__(256) main_kernel(const float* __restrict__ pitch,
                                                   const int*   __restrict__ beats,
                                                   const float* __restrict__ Wpitch,
                                                   const float* __restrict__ bpitch,
                                                   const float* __restrict__ embBeats,
                                                   float* __restrict__ out)
{
    int gid = blockIdx.x * 256 + threadIdx.x;
    int e4  = gid & 63;
    int bt  = gid >> 6;
    int t   = bt & (T_ - 1);
    int b   = bt >> 13;

    int  idx = g_idx[bt];
    float4 s = *(const float4*)&g_S[((size_t)(b*TP_ + idx))*E_ + e4*4];
    float4 p = *(const float4*)&g_P[(size_t)t*E_ + e4*4];
    float  pv = pitch[bt];
    int    bv = beats[bt];
    float4 wp = ((const float4*)Wpitch)[e4];
    float4 bp = ((const float4*)bpitch)[e4];
    float4 eb = *(const float4*)&embBeats[(size_t)bv*E_ + e4*4];

    float4 o;
    o.x = s.x + p.x + fmaf(pv, wp.x, bp.x) + eb.x;
    o.y = s.y + p.y + fmaf(pv, wp.y, bp.y) + eb.y;
    o.z = s.z + p.z + fmaf(pv, wp.z, bp.z) + eb.z;
    o.w = s.w + p.w + fmaf(pv, wp.w, bp.w) + eb.w;
    ((float4*)out)[gid] = o;
}

// =====================================================================
extern "C" void kernel_launch(void* const* d_in, const int* in_sizes, int n_in,
                              void* d_out, int out_size)
{
    const float* enc      = (const float*)d_in[0];
    const int*   align_p  = (const int*)  d_in[1];
    const int*   text_p   = (const int*)  d_in[2];
    const float* pitch    = (const float*)d_in[3];
    const int*   beats    = (const int*)  d_in[4];
    const float* W_pitch  = (const float*)d_in[5];
    const float* b_pitch  = (const float*)d_in[6];
    const float* W_pos    = (const float*)d_in[7];
    const float* b_pos    = (const float*)d_in[8];
    const float* emb_b    = (const float*)d_in[9];
    float* out = (float*)d_out;

    static int smem_set = 0;
    if (!smem_set) {
        cudaFuncSetAttribute(gemm_kernel,
                             cudaFuncAttributeMaxDynamicSharedMemorySize, SMEM_GEMM);
        smem_set = 1;
    }

    // PE (256) + parallel aligner (16) + W split (128) = 400 blocks
    prep_kernel<<<400, 512>>>(align_p, text_p, W_pos);

    gemm_kernel<<<M_TOT/128, 256, SMEM_GEMM>>>(enc, b_pos);

    main_kernel<<<(B_*T_*(E_/4)) / 256, 256>>>(pitch, beats, W_pitch, b_pitch,
                                               emb_b, out);
}

// round 9
// speedup vs baseline: 3.5825x; 1.1815x over previous
#include <cuda_runtime.h>
#include <cuda_bf16.h>
#include <cstdint>

#define B_  16
#define T_  8192
#define TP_ 512
#define E_  256
#define M_TOT (B_*TP_ + T_)     // 16384 GEMM rows: 8192 enc + 8192 pe
#define FULLMASK 0xFFFFFFFFu

// ---------------- device scratch (allocations are forbidden) ----------------
__device__ __align__(16) float          g_S [B_*TP_*E_];   // enc + enc@W_pos   (8 MB)
__device__ __align__(16) float          g_P [T_*E_];       // pe@W_pos + b_pos  (8 MB)
__device__ __align__(16) float          g_pe[T_*E_];       // sinusoid PE       (8 MB)
__device__ __align__(16) int            g_idx[B_*T_];      // aligner indices   (512 KB)
__device__ __align__(16) __nv_bfloat16  gBhi[E_*E_];       // W^T hi (128 KB)
__device__ __align__(16) __nv_bfloat16  gBlo[E_*E_];       // W^T lo (128 KB)

// ---------------- helpers ----------------
__device__ __forceinline__ uint32_t smem_u32(const void* p) {
    uint32_t a;
    asm("{ .reg .u64 t; cvta.to.shared.u64 t, %1; cvt.u32.u64 %0, t; }" : "=r"(a) : "l"(p));
    return a;
}
// SW64 swizzle: 64-byte rows, XOR bits [5:4] with bits [8:7]
#define SWZ64(x) ((x) ^ (((x) >> 3) & 0x30))

__device__ __forceinline__ void ldsm_x4(uint32_t& r0, uint32_t& r1, uint32_t& r2,
                                        uint32_t& r3, uint32_t addr) {
    asm volatile("ldmatrix.sync.aligned.m8n8.x4.shared.b16 {%0,%1,%2,%3}, [%4];"
                 : "=r"(r0), "=r"(r1), "=r"(r2), "=r"(r3) : "r"(addr));
}
__device__ __forceinline__ void mma_bf16(float* c, const uint32_t* a,
                                         uint32_t b0, uint32_t b1) {
    asm volatile(
        "mma.sync.aligned.m16n8k16.row.col.f32.bf16.bf16.f32 "
        "{%0,%1,%2,%3}, {%4,%5,%6,%7}, {%8,%9}, {%0,%1,%2,%3};"
        : "+f"(c[0]), "+f"(c[1]), "+f"(c[2]), "+f"(c[3])
        : "r"(a[0]), "r"(a[1]), "r"(a[2]), "r"(a[3]), "r"(b0), "r"(b1));
}
__device__ __forceinline__ uint32_t pack_bf2(float a, float b) {
    __nv_bfloat162 h(__float2bfloat16_rn(a), __float2bfloat16_rn(b));
    return *reinterpret_cast<uint32_t*>(&h);
}
__device__ __forceinline__ uint32_t pack_lo2(float a, float b) {
    __nv_bfloat16 ha = __float2bfloat16_rn(a), hb = __float2bfloat16_rn(b);
    return pack_bf2(a - __bfloat162float(ha), b - __bfloat162float(hb));
}

// =====================================================================
// Kernel 1 (prep):
//   blocks [0,256)   : sinusoid PE (fp32) via rotation trick
//   blocks [256,272) : parallel aligner (prefix-sum + validate, exact)
//   blocks [272,400) : W_pos transpose + bf16 hi/lo split
// =====================================================================
__global__ void __launch_bounds__(512) prep_kernel(const int* __restrict__ align_phone,
                                                   const int* __restrict__ text_phone,
                                                   const float* __restrict__ Wpos)
{
    int bid = blockIdx.x, tid = threadIdx.x;

    if (bid < 256) {
        // ---- sinusoid PE: 2 sincosf per 8 timesteps via rotation ----
        int g  = bid * 512 + tid;                  // [0, 131072)
        int i  = g & 127;
        int t0 = (g >> 7) * 8;
        const float NEGC = -0.03597789202637730f;  // -ln(10000)/E
        float div = expf((float)(2*i) * NEGC);
        float s, c, sd, cd;
        sincosf((float)t0 * div, &s, &c);
        sincosf(div, &sd, &cd);
        float2* row = ((float2*)g_pe) + (size_t)t0*128 + i;
        #pragma unroll
        for (int r = 0; r < 8; r++) {
            row[(size_t)r*128] = make_float2(s, c);
            float s2 = fmaf(s, cd,  c*sd);
            float c2 = fmaf(c, cd, -s*sd);
            s = s2; c = c2;
        }
        return;
    }
    if (bid >= 272) {
        // ---- W_pos transpose + split: Bt[n][k] = W[k][n] ----
        int idx = (bid - 272) * 512 + tid;         // [0, 65536)
        int k = idx >> 8, n = idx & 255;
        float w2 = Wpos[idx];
        __nv_bfloat16 wh = __float2bfloat16_rn(w2);
        gBhi[n*E_ + k] = wh;
        gBlo[n*E_ + k] = __float2bfloat16_rn(w2 - __bfloat162float(wh));
        return;
    }

    // ---------------- parallel aligner: block handles batch b ----------------
    __shared__ short stx[TP_];
    __shared__ int   wsum[16];
    __shared__ int   s_ok;
    int b = bid - 256;
    const int* arow = align_phone + (size_t)b * T_;
    int*       orow = g_idx       + (size_t)b * T_;

    for (int j = tid; j < TP_; j += 512) stx[j] = (short)text_phone[b*TP_ + j];
    if (tid == 0) s_ok = 1;
    __syncthreads();

    int base = tid * 16;
    int v[16];
    #pragma unroll
    for (int q = 0; q < 4; q++)
        *(int4*)&v[q*4] = *(const int4*)&arow[base + q*4];
    int prev = (base == 0) ? v[0] : arow[base - 1];

    unsigned cmask = 0;
    int cnt = 0;
    #pragma unroll
    for (int j = 0; j < 16; j++) {
        int c = (v[j] != prev) ? 1 : 0;
        if (base + j == 0) c = 0;
        cmask |= ((unsigned)c) << j;
        cnt += c;
        prev = v[j];
    }

    int lane = tid & 31, wId = tid >> 5;
    int incl = cnt;
    #pragma unroll
    for (int off = 1; off < 32; off <<= 1) {
        int nv = __shfl_up_sync(FULLMASK, incl, off);
        if (lane >= off) incl += nv;
    }
    if (lane == 31) wsum[wId] = incl;
    __syncthreads();
    if (tid == 0) {
        int a = 0;
        #pragma unroll
        for (int i = 0; i < 16; i++) { int t2 = wsum[i]; wsum[i] = a; a += t2; }
    }
    __syncthreads();
    int run = wsum[wId] + incl - cnt;

    bool ok = (base != 0) || (v[0] == (int)stx[0]);
    int outv[16];
    #pragma unroll
    for (int j = 0; j < 16; j++) {
        run += (int)((cmask >> j) & 1u);
        int ind = min(run, TP_ - 1);
        outv[j] = ind;
        if (base + j != 0) ok &= ((int)stx[ind] == v[j]);
    }
    #pragma unroll
    for (int q = 0; q < 4; q++)
        *(int4*)&orow[base + q*4] = *(const int4*)&outv[q*4];

    if (!ok) atomicAnd(&s_ok, 0);
    __syncthreads();
    if (s_ok == 0 && tid == 0) {
        int ind = 0, before = (int)stx[0];
        orow[0] = 0;
        for (int t = 1; t < T_; t++) {
            int a = arow[t];
            if (a != before) { ind = min(ind + 1, TP_ - 1); before = (int)stx[ind]; }
            orow[t] = ind;
        }
    }
}

// =====================================================================
// Kernel 2: bf16-split tensor-core GEMM via mma.sync (HMMA).
// D[16384,256] = Ahi@Bhi^T + Alo@Bhi^T + Ahi@Blo^T, fp32 accumulate.
// =====================================================================
#define AHI 0
#define ALO 8192
#define BHI 16384
#define BLO 32768
#define BUFSZ 49152
#define SMEM_GEMM (2*BUFSZ)

__global__ void __launch_bounds__(256, 1) gemm_kernel(const float* __restrict__ enc,
                                                      const float* __restrict__ bpos)
{
    extern __shared__ __align__(128) char smem[];
    uint32_t sb = smem_u32(smem);

    int tid  = threadIdx.x;
    int wid  = tid >> 5, lid = tid & 31;
    int wm   = wid & 1;
    int wn   = wid >> 1;
    int g    = lid >> 2, tig = lid & 3;
    int mBase = blockIdx.x * 128;
    bool isEnc = (mBase < B_*TP_);
    const float4* Afp = isEnc ? (const float4*)(enc + (size_t)mBase*E_)
                              : (const float4*)(g_pe + (size_t)(mBase - B_*TP_)*E_);

    float acc[4][8][4];
    #pragma unroll
    for (int t = 0; t < 4; t++)
        #pragma unroll
        for (int u = 0; u < 8; u++)
            #pragma unroll
            for (int q = 0; q < 4; q++) acc[t][u][q] = 0.f;

    auto load_slice = [&](int kc, int bsel) {
        char* buf = smem + bsel*BUFSZ;
        #pragma unroll
        for (int i = 0; i < 4; i++) {
            int idx = tid + i*256;
            int row = idx >> 3, c4 = idx & 7;
            float4 v = Afp[(size_t)row*64 + kc*8 + c4];
            uint2 hi, lo;
            hi.x = pack_bf2(v.x, v.y);  hi.y = pack_bf2(v.z, v.w);
            lo.x = pack_lo2(v.x, v.y);  lo.y = pack_lo2(v.z, v.w);
            uint32_t off = SWZ64((uint32_t)(row*64 + c4*8));
            *(uint2*)(buf + AHI + off) = hi;
            *(uint2*)(buf + ALO + off) = lo;
        }
        #pragma unroll
        for (int i = 0; i < 4; i++) {
            int idx = tid + i*256;
            int row = idx >> 2, c8 = idx & 3;
            uint32_t off = SWZ64((uint32_t)(row*64 + c8*16));
            *(uint4*)(buf + BHI + off) = ((const uint4*)gBhi)[(size_t)row*32 + kc*4 + c8];
            *(uint4*)(buf + BLO + off) = ((const uint4*)gBlo)[(size_t)row*32 + kc*4 + c8];
        }
    };

    load_slice(0, 0);
    __syncthreads();

    for (int kc = 0; kc < 8; kc++) {
        if (kc + 1 < 8) load_slice(kc + 1, (kc + 1) & 1);

        uint32_t ab = sb + (kc & 1)*BUFSZ;
        #pragma unroll
        for (int ks = 0; ks < 2; ks++) {
            uint32_t ah[4][4], bh[8][2], aw[4][4], bw[8][2];
            #pragma unroll
            for (int t = 0; t < 4; t++) {
                uint32_t off = (uint32_t)((wm*64 + t*16 + (lid & 15))*64
                                          + ks*32 + ((lid >> 4) & 1)*16);
                ldsm_x4(ah[t][0], ah[t][1], ah[t][2], ah[t][3], ab + AHI + SWZ64(off));
            }
            #pragma unroll
            for (int up = 0; up < 4; up++) {
                uint32_t off = (uint32_t)((wn*64 + up*16 + ((lid >> 4) & 1)*8
                                           + (lid & 7))*64
                                          + ks*32 + ((lid >> 3) & 1)*16);
                ldsm_x4(bh[2*up][0], bh[2*up][1], bh[2*up+1][0], bh[2*up+1][1],
                        ab + BHI + SWZ64(off));
            }
            #pragma unroll
            for (int t = 0; t < 4; t++)
                #pragma unroll
                for (int u = 0; u < 8; u++)
                    mma_bf16(acc[t][u], ah[t], bh[u][0], bh[u][1]);

            #pragma unroll
            for (int t = 0; t < 4; t++) {
                uint32_t off = (uint32_t)((wm*64 + t*16 + (lid & 15))*64
                                          + ks*32 + ((lid >> 4) & 1)*16);
                ldsm_x4(aw[t][0], aw[t][1], aw[t][2], aw[t][3], ab + ALO + SWZ64(off));
            }
            #pragma unroll
            for (int t = 0; t < 4; t++)
                #pragma unroll
                for (int u = 0; u < 8; u++)
                    mma_bf16(acc[t][u], aw[t], bh[u][0], bh[u][1]);

            #pragma unroll
            for (int up = 0; up < 4; up++) {
                uint32_t off = (uint32_t)((wn*64 + up*16 + ((lid >> 4) & 1)*8
                                           + (lid & 7))*64
                                          + ks*32 + ((lid >> 3) & 1)*16);
                ldsm_x4(bw[2*up][0], bw[2*up][1], bw[2*up+1][0], bw[2*up+1][1],
                        ab + BLO + SWZ64(off));
            }
            #pragma unroll
            for (int t = 0; t < 4; t++)
                #pragma unroll
                for (int u = 0; u < 8; u++)
                    mma_bf16(acc[t][u], ah[t], bw[u][0], bw[u][1]);
        }
        __syncthreads();
    }

    // ---- epilogue ----
    #pragma unroll
    for (int t = 0; t < 4; t++) {
        int rm = mBase + wm*64 + t*16 + g;
        #pragma unroll
        for (int u = 0; u < 8; u++) {
            int n  = wn*64 + u*8 + tig*2;
            int i0 = rm*128 + (n >> 1);
            int i1 = i0 + 8*128;
            if (isEnc) {
                float2 e0 = ((const float2*)enc)[i0];
                float2 e1 = ((const float2*)enc)[i1];
                ((float2*)g_S)[i0] = make_float2(acc[t][u][0] + e0.x,
                                                 acc[t][u][1] + e0.y);
                ((float2*)g_S)[i1] = make_float2(acc[t][u][2] + e1.x,
                                                 acc[t][u][3] + e1.y);
            } else {
                float2 bp = ((const float2*)bpos)[n >> 1];
                int j0 = i0 - B_*TP_*128;
                ((float2*)g_P)[j0]         = make_float2(acc[t][u][0] + bp.x,
                                                         acc[t][u][1] + bp.y);
                ((float2*)g_P)[j0 + 8*128] = make_float2(acc[t][u][2] + bp.x,
                                                         acc[t][u][3] + bp.y);
            }
        }
    }
}

// =====================================================================
// Kernel 3: chunk-reuse assemble.
// CTA = one 16-timestep chunk x all 16 batches x full E.
// P chunk in smem (read once); S rows hit L1 (16x reuse within CTA);
// per-e4 constants (W_pitch, b_pitch, emb_beats) live in registers.
// =====================================================================
__global__ void __launch_bounds__(256) main_kernel(const float* __restrict__ pitch,
                                                   const int*   __restrict__ beats,
                                                   const float* __restrict__ Wpitch,
                                                   const float* __restrict__ bpitch,
                                                   const float* __restrict__ embBeats,
                                                   float* __restrict__ out)
{
    __shared__ __align__(16) float sP[16*E_];     // 16 KB = 1024 float4
    __shared__ int   sidx  [256];                 // (b,tt) -> idx
    __shared__ float spitch[256];
    __shared__ int   sbeats[256];

    int tid = threadIdx.x;
    int t0  = blockIdx.x * 16;
    int e4  = tid & 63;
    int rp  = tid >> 6;                           // 0..3

    #pragma unroll
    for (int i = 0; i < 4; i++)                   // P chunk -> smem (1024 float4)
        ((float4*)sP)[tid + i*256] = ((const float4*)g_P)[(size_t)t0*64 + tid + i*256];
    {
        int b = tid >> 4, tt = tid & 15;
        int bt = b*T_ + t0 + tt;
        sidx[tid]   = g_idx[bt];
        spitch[tid] = pitch[bt];
        sbeats[tid] = beats[bt];
    }
    __syncthreads();

    float4 wp  = ((const float4*)Wpitch)[e4];
    float4 bp  = ((const float4*)bpitch)[e4];
    float4 eb0 = ((const float4*)embBeats)[e4];
    float4 eb1 = ((const float4*)embBeats)[64 + e4];

    #pragma unroll 4
    for (int i = 0; i < 64; i++) {
        int p  = i*4 + rp;                        // pair: b = p>>4, tt = p&15
        int b  = p >> 4, tt = p & 15;
        int ix = sidx[p];
        float4 s  = *(const float4*)&g_S[((size_t)(b*TP_ + ix))*E_ + e4*4];
        float4 pr = ((const float4*)sP)[tt*64 + e4];
        float  pv = spitch[p];
        float4 ev = sbeats[p] ? eb1 : eb0;
        float4 o;
        o.x = s.x + pr.x + fmaf(pv, wp.x, bp.x) + ev.x;
        o.y = s.y + pr.y + fmaf(pv, wp.y, bp.y) + ev.y;
        o.z = s.z + pr.z + fmaf(pv, wp.z, bp.z) + ev.z;
        o.w = s.w + pr.w + fmaf(pv, wp.w, bp.w) + ev.w;
        ((float4*)out)[((size_t)b*T_ + t0 + tt)*64 + e4] = o;
    }
}

// =====================================================================
extern "C" void kernel_launch(void* const* d_in, const int* in_sizes, int n_in,
                              void* d_out, int out_size)
{
    const float* enc      = (const float*)d_in[0];
    const int*   align_p  = (const int*)  d_in[1];
    const int*   text_p   = (const int*)  d_in[2];
    const float* pitch    = (const float*)d_in[3];
    const int*   beats    = (const int*)  d_in[4];
    const float* W_pitch  = (const float*)d_in[5];
    const float* b_pitch  = (const float*)d_in[6];
    const float* W_pos    = (const float*)d_in[7];
    const float* b_pos    = (const float*)d_in[8];
    const float* emb_b    = (const float*)d_in[9];
    float* out = (float*)d_out;

    static int smem_set = 0;
    if (!smem_set) {
        cudaFuncSetAttribute(gemm_kernel,
                             cudaFuncAttributeMaxDynamicSharedMemorySize, SMEM_GEMM);
        smem_set = 1;
    }

    prep_kernel<<<400, 512>>>(align_p, text_p, W_pos);
    gemm_kernel<<<M_TOT/128, 256, SMEM_GEMM>>>(enc, b_pos);
    main_kernel<<<T_/16, 256>>>(pitch, beats, W_pitch, b_pitch, emb_b, out);
}